// round 4
// baseline (speedup 1.0000x reference)
#include <cuda_runtime.h>

#define NN 1024
#define EE 2048
#define CIN 4
#define HID 192
#define KCH 5
#define NL 4
#define NAUG 1152          // 5*HID (edge basis) + HID (root)

typedef unsigned long long ull;

// ---------------- device scratch (allocation-free) ----------------
__device__ float g_S[4*NN*CIN];       // S_k = lap(T_{k-1}), k=1..4
__device__ float g_h0[NN*HID];
__device__ float g_h1[NN*HID];
__device__ float g_Y[NN*NAUG];
__device__ float g_B[NL][HID*NAUG];   // B[i][j*1152 + k*192 + o] (k<5: Weff, cols 960+: root)

// ---------------- f32x2 helpers ----------------
__device__ __forceinline__ void fma2(ull &c, ull a, ull b) {
    asm("fma.rn.f32x2 %0, %1, %2, %0;" : "+l"(c) : "l"(a), "l"(b));
}
__device__ __forceinline__ ull pk2(float a) {
    ull r; asm("mov.b64 %0, {%1, %1};" : "=l"(r) : "f"(a)); return r;
}
__device__ __forceinline__ float2 up2(ull a) {
    float2 f; asm("mov.b64 {%0, %1}, %2;" : "=f"(f.x), "=f"(f.y) : "l"(a)); return f;
}

// ---------------- single-block Cheb prep: deg, dinv, 4 scatter rounds (smem) ----------------
// S_k = lap(T_{k-1});  T0=x, T1=S1, T2=2S2-x, T3=2S3-S1, T4=2S4-2S2+x
__global__ void k_cheb_prep(const int* __restrict__ ei, const float* __restrict__ x) {
    extern __shared__ float sm[];
    float* sdeg = sm;          // [1024]
    float* sS   = sm + NN;     // [4][1024][4]
    int t = threadIdx.x;       // 1024 threads

    sdeg[t] = 0.f;
    #pragma unroll
    for (int r = 0; r < 16; r++) sS[t + r*NN] = 0.f;
    __syncthreads();

    int e0 = t, e1 = t + NN;
    int s0 = ei[e0], s1 = ei[e1];
    int d0 = ei[EE + e0], d1 = ei[EE + e1];
    atomicAdd(&sdeg[s0], 1.f);
    atomicAdd(&sdeg[s1], 1.f);
    __syncthreads();
    float dv = sdeg[t];
    float di = dv > 0.f ? rsqrtf(dv) : 0.f;
    __syncthreads();
    sdeg[t] = di;
    __syncthreads();

    float w0 = -sdeg[s0] * sdeg[d0];
    float w1 = -sdeg[s1] * sdeg[d1];
    float4 x0 = *(const float4*)(x + s0*4);
    float4 x1 = *(const float4*)(x + s1*4);

    // k=1: S0 += w * x[src]
    atomicAdd(&sS[d0*4+0], w0*x0.x); atomicAdd(&sS[d0*4+1], w0*x0.y);
    atomicAdd(&sS[d0*4+2], w0*x0.z); atomicAdd(&sS[d0*4+3], w0*x0.w);
    atomicAdd(&sS[d1*4+0], w1*x1.x); atomicAdd(&sS[d1*4+1], w1*x1.y);
    atomicAdd(&sS[d1*4+2], w1*x1.z); atomicAdd(&sS[d1*4+3], w1*x1.w);
    __syncthreads();
    // k=2: S1 += w * S0[src]
    #pragma unroll
    for (int c = 0; c < 4; c++) {
        float v0 = sS[s0*4+c], v1 = sS[s1*4+c];
        atomicAdd(&sS[4096 + d0*4+c], w0*v0);
        atomicAdd(&sS[4096 + d1*4+c], w1*v1);
    }
    __syncthreads();
    // k=3: S2 += w * (2*S1[src] - x[src])
    {
        float xv0[4] = {x0.x, x0.y, x0.z, x0.w};
        float xv1[4] = {x1.x, x1.y, x1.z, x1.w};
        #pragma unroll
        for (int c = 0; c < 4; c++) {
            float v0 = 2.f*sS[4096 + s0*4+c] - xv0[c];
            float v1 = 2.f*sS[4096 + s1*4+c] - xv1[c];
            atomicAdd(&sS[2*4096 + d0*4+c], w0*v0);
            atomicAdd(&sS[2*4096 + d1*4+c], w1*v1);
        }
    }
    __syncthreads();
    // k=4: S3 += w * (2*S2[src] - S0[src])
    #pragma unroll
    for (int c = 0; c < 4; c++) {
        float v0 = 2.f*sS[2*4096 + s0*4+c] - sS[s0*4+c];
        float v1 = 2.f*sS[2*4096 + s1*4+c] - sS[s1*4+c];
        atomicAdd(&sS[3*4096 + d0*4+c], w0*v0);
        atomicAdd(&sS[3*4096 + d1*4+c], w1*v1);
    }
    __syncthreads();

    #pragma unroll
    for (int r = 0; r < 16; r++) g_S[t + r*NN] = sS[t + r*NN];
}

// ---------------- Cheb output: h0 = sum_k T_k @ W_k + b ----------------
__global__ void k_cheb_out(const float* __restrict__ x,
                           const float* __restrict__ cw, const float* __restrict__ cb) {
    int n = blockIdx.x, o = threadIdx.x;   // 1024 x 192
    __shared__ float tx[KCH][CIN];
    if (o < CIN) {
        float xv = x[n*CIN + o];
        float s1 = g_S[n*4+o], s2 = g_S[4096 + n*4+o];
        float s3 = g_S[2*4096 + n*4+o], s4 = g_S[3*4096 + n*4+o];
        tx[0][o] = xv;
        tx[1][o] = s1;
        tx[2][o] = 2.f*s2 - xv;
        tx[3][o] = 2.f*s3 - s1;
        tx[4][o] = 2.f*s4 - 2.f*s2 + xv;
    }
    __syncthreads();
    float acc = cb[o];
    #pragma unroll
    for (int k = 0; k < KCH; k++)
        #pragma unroll
        for (int c = 0; c < CIN; c++)
            acc += tx[k][c] * cw[(k*CIN + c)*HID + o];
    g_h0[n*HID + o] = acc;
}

// ---------------- k_M: G inline + Mstack + root copy ----------------
__global__ void __launch_bounds__(256) k_M(const float* __restrict__ nn2_w,
                                           const float* __restrict__ nn2_b,
                                           const float* __restrict__ eenc_w,
                                           const float* __restrict__ eenc_b,
                                           const float* __restrict__ nn1_w,
                                           const float* __restrict__ nn1_b,
                                           const float* __restrict__ root_w) {
    int i = blockIdx.y;
    int t = threadIdx.x;
    __shared__ float2 sG[5*HID];
    // inline G = [eenc_w; eenc_b-path] @ nn1_w (threads 0..191)
    if (t < HID) {
        float acc[5] = {0.f, 0.f, 0.f, 0.f, 0.f};
        const float* W = nn1_w + i*HID*HID;
        for (int j0 = 0; j0 < HID; j0++) {
            float w = W[j0*HID + t];
            acc[0] += eenc_w[j0]*w;
            acc[1] += eenc_w[HID + j0]*w;
            acc[2] += eenc_w[2*HID + j0]*w;
            acc[3] += eenc_w[3*HID + j0]*w;
            acc[4] += eenc_b[j0]*w;
        }
        acc[4] += nn1_b[i*HID + t];
        #pragma unroll
        for (int k = 0; k < 5; k++) sG[k*HID + t] = make_float2(acc[k], acc[k]);
    }
    // root copy into g_B cols 960..1151 (1 float4 per thread)
    {
        int m = blockIdx.x*1024 + t*4;
        int j = m / HID, o = m - j*HID;
        float4 v = *(const float4*)(root_w + (size_t)i*HID*HID + m);
        *(float4*)(g_B[i] + j*NAUG + 5*HID + o) = v;
    }
    __syncthreads();

    int m4 = (blockIdx.x*256 + t) * 4;   // 0..36860
    const float* W = nn2_w + (size_t)i * HID * (HID*HID);
    ull acc[5][2] = {};
    #pragma unroll 4
    for (int j = 0; j < HID; j++) {
        float4 v = __ldg((const float4*)(W + (size_t)j*(HID*HID) + m4));
        ull v01, v23;
        asm("mov.b64 %0, {%1, %2};" : "=l"(v01) : "f"(v.x), "f"(v.y));
        asm("mov.b64 %0, {%1, %2};" : "=l"(v23) : "f"(v.z), "f"(v.w));
        #pragma unroll
        for (int k = 0; k < 5; k++) {
            ull gk = *(const ull*)&sG[k*HID + j];
            fma2(acc[k][0], gk, v01);
            fma2(acc[k][1], gk, v23);
        }
    }
    float4 b = __ldg((const float4*)(nn2_b + (size_t)i*(HID*HID) + m4));
    float2 a40 = up2(acc[4][0]), a41 = up2(acc[4][1]);
    a40.x += b.x; a40.y += b.y; a41.x += b.z; a41.y += b.w;
    int j2 = m4 / HID;
    int o  = m4 - j2 * HID;
    float* dst = g_B[i] + j2*NAUG + o;
    #pragma unroll
    for (int k = 0; k < 4; k++) {
        *(float2*)(dst + k*HID)     = up2(acc[k][0]);
        *(float2*)(dst + k*HID + 2) = up2(acc[k][1]);
    }
    *(float2*)(dst + 4*HID)     = a40;
    *(float2*)(dst + 4*HID + 2) = a41;
}

// ---------------- fused LN+ReLU + node GEMM ----------------
// Y[1024,1152] = LN(h_in)[1024,192] @ B[192,1152]
// smem: sA[192][130] (full-K A, LN'd), sB[192][68] (full-K B tile)
// Epilogue: cols<960 -> g_Y ; cols>=960 -> h_out = root + cb (+ h_in if resid)
#define SMEM_GEMM ((192*130 + 192*68)*4)
__global__ void __launch_bounds__(256)
k_gemm(int layer, int do_ln, int resid,
       const float* __restrict__ lng, const float* __restrict__ lnb,
       const float* __restrict__ cb) {
    extern __shared__ float sm[];
    float* sA = sm;              // k*130 + m
    float* sB = sm + 192*130;    // k*68 + c
    const float* hin  = (layer & 1) ? g_h1 : g_h0;
    float*       hout = (layer & 1) ? g_h0 : g_h1;
    const float* B = g_B[layer];
    int t = threadIdx.x;
    int m0 = blockIdx.x * 128;   // grid.x = 8
    int n0 = blockIdx.y * 64;    // grid.y = 18
    int warp = t >> 5, lane = t & 31;

    // B tile (full K): 3072 float4 / 256 threads
    #pragma unroll
    for (int r = 0; r < 12; r++) {
        int q = t + r*256;
        int kk = q >> 4, c4 = q & 15;
        float4 v = __ldg((const float4*)(B + kk*NAUG + n0 + c4*4));
        *(float4*)&sB[kk*68 + c4*4] = v;
    }

    // A tile with fused LN+ReLU (one warp per row)
    float gg[6], bb[6];
    if (do_ln) {
        #pragma unroll
        for (int i = 0; i < 6; i++) { gg[i] = lng[lane + 32*i]; bb[i] = lnb[lane + 32*i]; }
    }
    for (int r = warp; r < 128; r += 8) {
        const float* row = hin + (size_t)(m0 + r)*HID;
        float v[6];
        #pragma unroll
        for (int i = 0; i < 6; i++) v[i] = row[lane + 32*i];
        if (do_ln) {
            float s = v[0]+v[1]+v[2]+v[3]+v[4]+v[5];
            #pragma unroll
            for (int o = 16; o > 0; o >>= 1) s += __shfl_xor_sync(0xffffffffu, s, o);
            float mu = s * (1.f/192.f);
            float q2 = 0.f;
            #pragma unroll
            for (int i = 0; i < 6; i++) { float d = v[i]-mu; q2 += d*d; }
            #pragma unroll
            for (int o = 16; o > 0; o >>= 1) q2 += __shfl_xor_sync(0xffffffffu, q2, o);
            float rs = rsqrtf(q2*(1.f/192.f) + 1e-5f);
            #pragma unroll
            for (int i = 0; i < 6; i++)
                v[i] = fmaxf(0.f, (v[i]-mu)*rs*gg[i] + bb[i]);
        }
        #pragma unroll
        for (int i = 0; i < 6; i++) sA[(lane + 32*i)*130 + r] = v[i];
    }
    __syncthreads();

    int ty = t >> 4, tx = t & 15;
    ull acc[8][2] = {};
    #pragma unroll 4
    for (int kk = 0; kk < 192; kk++) {
        ull b0 = *(const ull*)&sB[kk*68 + tx*4];
        ull b1 = *(const ull*)&sB[kk*68 + tx*4 + 2];
        const float* ar = &sA[kk*130 + ty*8];
        #pragma unroll
        for (int p = 0; p < 8; p++) {
            ull ap = pk2(ar[p]);
            fma2(acc[p][0], ap, b0);
            fma2(acc[p][1], ap, b1);
        }
    }

    if (n0 < 5*HID) {
        #pragma unroll
        for (int p = 0; p < 8; p++) {
            float* yp = g_Y + (size_t)(m0 + ty*8 + p)*NAUG + n0 + tx*4;
            *(float2*)(yp)     = up2(acc[p][0]);
            *(float2*)(yp + 2) = up2(acc[p][1]);
        }
    } else {
        int ob = n0 - 5*HID + tx*4;
        float c0 = cb[ob], c1 = cb[ob+1], c2 = cb[ob+2], c3 = cb[ob+3];
        #pragma unroll
        for (int p = 0; p < 8; p++) {
            int m = m0 + ty*8 + p;
            float2 v0 = up2(acc[p][0]);
            float2 v1 = up2(acc[p][1]);
            float r0 = v0.x + c0, r1 = v0.y + c1, r2 = v1.x + c2, r3 = v1.y + c3;
            if (resid) {
                const float* hp = hin + (size_t)m*HID + ob;
                r0 += hp[0]; r1 += hp[1]; r2 += hp[2]; r3 += hp[3];
            }
            float* op = hout + (size_t)m*HID + ob;
            op[0] = r0; op[1] = r1; op[2] = r2; op[3] = r3;
        }
    }
}

// ---------------- per-edge combine + scatter ----------------
__global__ void k_escatter(int layer, const int* __restrict__ ei, const float* __restrict__ attr) {
    float* hout = (layer & 1) ? g_h0 : g_h1;
    int e = blockIdx.x;            // 2048 blocks
    int o = threadIdx.x;           // 192
    int s = ei[e], d = ei[EE + e];
    float4 a = __ldg((const float4*)(attr + e*4));
    const float* Ys = g_Y + (size_t)s*NAUG;
    float v = Ys[4*HID + o]
            + a.x*Ys[o] + a.y*Ys[HID + o] + a.z*Ys[2*HID + o] + a.w*Ys[3*HID + o];
    atomicAdd(&hout[d*HID + o], v);
}

// ---------------- fused final LN + head ----------------
__global__ void k_out(const float* __restrict__ lng, const float* __restrict__ lnb,
                      const float* __restrict__ ow, const float* __restrict__ ob,
                      float* __restrict__ out) {
    int n = blockIdx.x, t = threadIdx.x;    // 1024 x 192
    __shared__ float red[6];
    __shared__ float r0s[6], r1s[6];
    int warp = t >> 5, lane = t & 31;
    float v = g_h0[n*HID + t];
    float s = v;
    #pragma unroll
    for (int o = 16; o > 0; o >>= 1) s += __shfl_xor_sync(0xffffffffu, s, o);
    if (lane == 0) red[warp] = s;
    __syncthreads();
    float tot = 0.f;
    #pragma unroll
    for (int w = 0; w < 6; w++) tot += red[w];
    float mu = tot * (1.f/192.f);
    float d = v - mu;
    float s2 = d * d;
    #pragma unroll
    for (int o = 16; o > 0; o >>= 1) s2 += __shfl_xor_sync(0xffffffffu, s2, o);
    __syncthreads();
    if (lane == 0) red[warp] = s2;
    __syncthreads();
    float var = 0.f;
    #pragma unroll
    for (int w = 0; w < 6; w++) var += red[w];
    var *= (1.f/192.f);
    float z = fmaxf(0.f, d * rsqrtf(var + 1e-5f) * lng[t] + lnb[t]);
    float p0 = z * ow[t*2];
    float p1 = z * ow[t*2 + 1];
    #pragma unroll
    for (int o = 16; o > 0; o >>= 1) {
        p0 += __shfl_xor_sync(0xffffffffu, p0, o);
        p1 += __shfl_xor_sync(0xffffffffu, p1, o);
    }
    if (lane == 0) { r0s[warp] = p0; r1s[warp] = p1; }
    __syncthreads();
    if (t == 0) {
        float a0 = ob[0], a1 = ob[1];
        #pragma unroll
        for (int w = 0; w < 6; w++) { a0 += r0s[w]; a1 += r1s[w]; }
        out[n*2]     = a0;
        out[n*2 + 1] = a1;
    }
}

// ---------------- launcher ----------------
extern "C" void kernel_launch(void* const* d_in, const int* in_sizes, int n_in,
                              void* d_out, int out_size) {
    const float* x       = (const float*)d_in[0];
    const int*   ei      = (const int*)  d_in[1];
    const float* attr    = (const float*)d_in[2];
    const float* cheb_w  = (const float*)d_in[4];
    const float* cheb_b  = (const float*)d_in[5];
    const float* eenc_w  = (const float*)d_in[6];
    const float* eenc_b  = (const float*)d_in[7];
    const float* nn1_w   = (const float*)d_in[8];
    const float* nn1_b   = (const float*)d_in[9];
    const float* nn2_w   = (const float*)d_in[10];
    const float* nn2_b   = (const float*)d_in[11];
    const float* root_w  = (const float*)d_in[12];
    const float* conv_b  = (const float*)d_in[13];
    const float* ln_g    = (const float*)d_in[14];
    const float* ln_b    = (const float*)d_in[15];
    const float* out_w   = (const float*)d_in[16];
    const float* out_b   = (const float*)d_in[17];
    float* out = (float*)d_out;

    static int init = 0;
    if (!init) {
        cudaFuncSetAttribute(k_gemm, cudaFuncAttributeMaxDynamicSharedMemorySize, SMEM_GEMM);
        cudaFuncSetAttribute(k_cheb_prep, cudaFuncAttributeMaxDynamicSharedMemorySize,
                             (NN + 4*NN*CIN)*4);
        init = 1;
    }

    // edge-MLP linearization (G inline, root copy folded in)
    k_M<<<dim3(36, NL), 256>>>(nn2_w, nn2_b, eenc_w, eenc_b, nn1_w, nn1_b, root_w);

    // ChebConv (single-block prep + output)
    k_cheb_prep<<<1, 1024, (NN + 4*NN*CIN)*4>>>(ei, x);
    k_cheb_out<<<NN, HID>>>(x, cheb_w, cheb_b);

    // 4 NNConv layers: fused LN+GEMM, then edge combine/scatter
    for (int i = 0; i < NL; i++) {
        k_gemm<<<dim3(8, 18), 256, SMEM_GEMM>>>(i, i > 0, i > 0,
                                                ln_g + i*HID, ln_b + i*HID,
                                                conv_b + i*HID);
        k_escatter<<<EE, HID>>>(i, ei, attr);
    }

    // fused final LN + head
    k_out<<<NN, HID>>>(ln_g, ln_b, out_w, out_b, out);
}